// round 5
// baseline (speedup 1.0000x reference)
#include <cuda_runtime.h>
#include <math.h>

// Problem constants
#define BQ      4
#define NT      4096
#define CC      768
#define NHEADS  12
#define NPTS    4
#define HDIM    64
#define HIDDEN  3072
#define MROWS   (BQ*NT)          // 16384
#define SCALE_ATTN 0.125f        // 64^-0.5

// ---------------- scratch (device globals; no cudaMalloc allowed) ----------
__device__ float g_h[(size_t)MROWS * CC];          // ln1 out / ln2 out (reused)
__device__ float g_qkv[(size_t)MROWS * 3 * CC];    // qkv
__device__ float g_off[(size_t)MROWS * NHEADS * NPTS * 2];
__device__ float g_attn[(size_t)MROWS * CC];       // attention output
__device__ float g_mlp[(size_t)MROWS * HIDDEN];    // gelu(fc1)

// ---------------- LayerNorm: one 256-thread block per row (768 elems) ------
__global__ __launch_bounds__(256) void layernorm_kernel(
    const float* __restrict__ x, const float* __restrict__ w,
    const float* __restrict__ b, float* __restrict__ out)
{
    int row = blockIdx.x;
    int t = threadIdx.x;
    const float* xr = x + (size_t)row * CC;
    float v0 = xr[t], v1 = xr[t + 256], v2 = xr[t + 512];
    float s  = v0 + v1 + v2;
    float sq = v0*v0 + v1*v1 + v2*v2;

    __shared__ float sh[16];
    #pragma unroll
    for (int o = 16; o > 0; o >>= 1) {
        s  += __shfl_xor_sync(0xffffffffu, s,  o);
        sq += __shfl_xor_sync(0xffffffffu, sq, o);
    }
    int wid = t >> 5, lane = t & 31;
    if (lane == 0) { sh[wid] = s; sh[8 + wid] = sq; }
    __syncthreads();
    if (t == 0) {
        float ts = 0.f, tq = 0.f;
        #pragma unroll
        for (int i = 0; i < 8; i++) { ts += sh[i]; tq += sh[8 + i]; }
        sh[0] = ts; sh[8] = tq;
    }
    __syncthreads();
    float mean = sh[0] * (1.0f / CC);
    float var  = sh[8] * (1.0f / CC) - mean * mean;
    float rstd = rsqrtf(var + 1e-5f);
    float* orow = out + (size_t)row * CC;
    orow[t]       = (v0 - mean) * rstd * w[t]       + b[t];
    orow[t + 256] = (v1 - mean) * rstd * w[t + 256] + b[t + 256];
    orow[t + 512] = (v2 - mean) * rstd * w[t + 512] + b[t + 512];
}

// ---------------- SGEMM: C[M,N] = A[M,K] * W[N,K]^T + bias (+epilogue) -----
// EPI: 0 = bias, 1 = bias + exact GELU, 2 = bias + residual add
template<int EPI>
__global__ __launch_bounds__(256) void sgemm_nt(
    const float* __restrict__ A, int lda,
    const float* __restrict__ Bw,            // [N, K], K contiguous
    const float* __restrict__ bias,
    const float* __restrict__ Res, int ldr,
    float* __restrict__ C, int ldc,
    int M, int N, int K)
{
    __shared__ float As[8][128];
    __shared__ float Bs[8][128];

    int t = threadIdx.x;
    int rowTile = blockIdx.y * 128;
    int colTile = blockIdx.x * 128;

    int ldRow = t >> 1;            // 0..127
    int ldCol = (t & 1) * 4;       // 0 or 4

    const float* Aptr = A + (size_t)(rowTile + ldRow) * lda + ldCol;
    bool bValid = (colTile + ldRow) < N;
    const float* Bptr = Bw + (size_t)(colTile + ldRow) * K + ldCol;

    int ty = t >> 4, tx = t & 15;
    float acc[8][8];
    #pragma unroll
    for (int i = 0; i < 8; i++)
        #pragma unroll
        for (int j = 0; j < 8; j++) acc[i][j] = 0.f;

    for (int k0 = 0; k0 < K; k0 += 8) {
        float4 av = *(const float4*)(Aptr + k0);
        float4 bv = bValid ? *(const float4*)(Bptr + k0)
                           : make_float4(0.f, 0.f, 0.f, 0.f);
        As[ldCol + 0][ldRow] = av.x; As[ldCol + 1][ldRow] = av.y;
        As[ldCol + 2][ldRow] = av.z; As[ldCol + 3][ldRow] = av.w;
        Bs[ldCol + 0][ldRow] = bv.x; Bs[ldCol + 1][ldRow] = bv.y;
        Bs[ldCol + 2][ldRow] = bv.z; Bs[ldCol + 3][ldRow] = bv.w;
        __syncthreads();

        #pragma unroll
        for (int k = 0; k < 8; k++) {
            float4 a0 = *(const float4*)&As[k][ty * 8];
            float4 a1 = *(const float4*)&As[k][ty * 8 + 4];
            float4 b0 = *(const float4*)&Bs[k][tx * 8];
            float4 b1 = *(const float4*)&Bs[k][tx * 8 + 4];
            float ar[8] = {a0.x, a0.y, a0.z, a0.w, a1.x, a1.y, a1.z, a1.w};
            float br[8] = {b0.x, b0.y, b0.z, b0.w, b1.x, b1.y, b1.z, b1.w};
            #pragma unroll
            for (int i = 0; i < 8; i++)
                #pragma unroll
                for (int j = 0; j < 8; j++)
                    acc[i][j] = fmaf(ar[i], br[j], acc[i][j]);
        }
        __syncthreads();
    }

    #pragma unroll
    for (int i = 0; i < 8; i++) {
        int r = rowTile + ty * 8 + i;
        float* crow = C + (size_t)r * ldc;
        const float* rrow = (EPI == 2) ? (Res + (size_t)r * ldr) : nullptr;
        #pragma unroll
        for (int j = 0; j < 8; j++) {
            int c = colTile + tx * 8 + j;
            if (c < N) {
                float v = acc[i][j] + bias[c];
                if (EPI == 1) v = 0.5f * v * (1.0f + erff(v * 0.70710678118654752f));
                if (EPI == 2) v += rrow[c];
                crow[c] = v;
            }
        }
    }
}

// ---------------- deformable sampling + attention --------------------------
// grid: (B*N, HEADS), 32 threads. lane owns channels d and d+32.
__global__ __launch_bounds__(32) void attn_kernel(
    const float* __restrict__ qkv,    // [M, 2304]
    const float* __restrict__ off,    // [M, 96]
    const float* __restrict__ refp,   // [M, 2]
    float* __restrict__ out,          // [M, 768]
    const int* __restrict__ Hp, const int* __restrict__ Wp)
{
    int bn   = blockIdx.x;            // b*NT + n
    int head = blockIdx.y;
    int lane = threadIdx.x;
    int b = bn / NT;

    int H = *Hp, W = *Wp;
    float fW = (float)W, fH = (float)H;

    size_t qbase = (size_t)bn * (3 * CC) + head * HDIM;
    float q0 = qkv[qbase + lane];
    float q1 = qkv[qbase + lane + 32];

    float ref0 = refp[(size_t)bn * 2 + 0];
    float ref1 = refp[(size_t)bn * 2 + 1];

    const float* offp = off + (size_t)bn * (NHEADS * NPTS * 2) + head * (NPTS * 2);

    float dots[NPTS];
    float sv0[NPTS], sv1[NPTS];

    #pragma unroll
    for (int p = 0; p < NPTS; p++) {
        float o0 = offp[p * 2 + 0];
        float o1 = offp[p * 2 + 1];
        float gx = 2.0f * (ref0 + o0 / fW) - 1.0f;
        float gy = 2.0f * (ref1 + o1 / fH) - 1.0f;
        float x = ((gx + 1.0f) * fW - 1.0f) * 0.5f;
        float y = ((gy + 1.0f) * fH - 1.0f) * 0.5f;
        float x0f = floorf(x), y0f = floorf(y);
        float wx = x - x0f, wy = y - y0f;
        int x0 = (int)x0f, y0 = (int)y0f;

        float cw[4] = {(1.f - wx) * (1.f - wy), wx * (1.f - wy),
                       (1.f - wx) * wy,          wx * wy};
        int cx[4] = {x0, x0 + 1, x0,     x0 + 1};
        int cy[4] = {y0, y0,     y0 + 1, y0 + 1};

        float sk0 = 0.f, sk1 = 0.f, vv0 = 0.f, vv1 = 0.f;
        #pragma unroll
        for (int c = 0; c < 4; c++) {
            int ix = cx[c], iy = cy[c];
            if (ix >= 0 && ix < W && iy >= 0 && iy < H) {
                size_t rb = ((size_t)(b * NT + iy * W + ix)) * (3 * CC) + head * HDIM;
                const float* kp = qkv + rb + CC;       // k section
                const float* vp = qkv + rb + 2 * CC;   // v section
                float w = cw[c];
                sk0 = fmaf(w, kp[lane],      sk0);
                sk1 = fmaf(w, kp[lane + 32], sk1);
                vv0 = fmaf(w, vp[lane],      vv0);
                vv1 = fmaf(w, vp[lane + 32], vv1);
            }
        }
        sv0[p] = vv0; sv1[p] = vv1;

        float dot = q0 * sk0 + q1 * sk1;
        #pragma unroll
        for (int o = 16; o > 0; o >>= 1)
            dot += __shfl_xor_sync(0xffffffffu, dot, o);
        dots[p] = dot * SCALE_ATTN;
    }

    // softmax over 4 points (all lanes hold the full dots)
    float mx = fmaxf(fmaxf(dots[0], dots[1]), fmaxf(dots[2], dots[3]));
    float e[NPTS], es = 0.f;
    #pragma unroll
    for (int p = 0; p < NPTS; p++) { e[p] = __expf(dots[p] - mx); es += e[p]; }
    float inv = 1.0f / es;

    float out0 = 0.f, out1 = 0.f;
    #pragma unroll
    for (int p = 0; p < NPTS; p++) {
        float a = e[p] * inv;
        out0 = fmaf(a, sv0[p], out0);
        out1 = fmaf(a, sv1[p], out1);
    }
    size_t ob = (size_t)bn * CC + head * HDIM;
    out[ob + lane]      = out0;
    out[ob + lane + 32] = out1;
}

// ---------------- launch ----------------------------------------------------
extern "C" void kernel_launch(void* const* d_in, const int* in_sizes, int n_in,
                              void* d_out, int out_size)
{
    const float* x      = (const float*)d_in[0];
    const float* refp   = (const float*)d_in[1];
    const float* n1w    = (const float*)d_in[2];
    const float* n1b    = (const float*)d_in[3];
    const float* qkv_w  = (const float*)d_in[4];
    const float* qkv_b  = (const float*)d_in[5];
    const float* off_w  = (const float*)d_in[6];
    const float* off_b  = (const float*)d_in[7];
    const float* proj_w = (const float*)d_in[8];
    const float* proj_b = (const float*)d_in[9];
    const float* n2w    = (const float*)d_in[10];
    const float* n2b    = (const float*)d_in[11];
    const float* fc1_w  = (const float*)d_in[12];
    const float* fc1_b  = (const float*)d_in[13];
    const float* fc2_w  = (const float*)d_in[14];
    const float* fc2_b  = (const float*)d_in[15];
    const int*   Hp     = (const int*)d_in[16];
    const int*   Wp     = (const int*)d_in[17];
    float* out = (float*)d_out;

    float* h    = nullptr; cudaGetSymbolAddress((void**)&h,    g_h);
    float* qkv  = nullptr; cudaGetSymbolAddress((void**)&qkv,  g_qkv);
    float* offb = nullptr; cudaGetSymbolAddress((void**)&offb, g_off);
    float* attn = nullptr; cudaGetSymbolAddress((void**)&attn, g_attn);
    float* mlp  = nullptr; cudaGetSymbolAddress((void**)&mlp,  g_mlp);

    // 1) ln1: x -> h
    layernorm_kernel<<<MROWS, 256>>>(x, n1w, n1b, h);

    // 2) qkv = h @ qkv_w^T + b : [16384, 2304]
    {
        dim3 grid((3 * CC + 127) / 128, MROWS / 128);
        sgemm_nt<0><<<grid, 256>>>(h, CC, qkv_w, qkv_b,
                                   nullptr, 0, qkv, 3 * CC,
                                   MROWS, 3 * CC, CC);
    }

    // 3) offsets = q @ off_w^T + off_b : [16384, 96]  (q = first 768 cols of qkv)
    {
        dim3 grid(1, MROWS / 128);
        sgemm_nt<0><<<grid, 256>>>(qkv, 3 * CC, off_w, off_b,
                                   nullptr, 0, offb, NHEADS * NPTS * 2,
                                   MROWS, NHEADS * NPTS * 2, CC);
    }

    // 4) deformable sampling + attention -> attn [16384, 768]
    {
        dim3 grid(BQ * NT, NHEADS);
        attn_kernel<<<grid, 32>>>(qkv, offb, refp, attn, Hp, Wp);
    }

    // 5) x1 = x + attn @ proj_w^T + proj_b -> out
    {
        dim3 grid(CC / 128, MROWS / 128);
        sgemm_nt<2><<<grid, 256>>>(attn, CC, proj_w, proj_b,
                                   x, CC, out, CC,
                                   MROWS, CC, CC);
    }

    // 6) ln2: out -> h
    layernorm_kernel<<<MROWS, 256>>>(out, n2w, n2b, h);

    // 7) m = gelu(h @ fc1_w^T + fc1_b) -> mlp [16384, 3072]
    {
        dim3 grid(HIDDEN / 128, MROWS / 128);
        sgemm_nt<1><<<grid, 256>>>(h, CC, fc1_w, fc1_b,
                                   nullptr, 0, mlp, HIDDEN,
                                   MROWS, HIDDEN, CC);
    }

    // 8) out = out + mlp @ fc2_w^T + fc2_b
    {
        dim3 grid(CC / 128, MROWS / 128);
        sgemm_nt<2><<<grid, 256>>>(mlp, HIDDEN, fc2_w, fc2_b,
                                   out, CC, out, CC,
                                   MROWS, CC, HIDDEN);
    }
}

// round 6
// speedup vs baseline: 2.9952x; 2.9952x over previous
#include <cuda_runtime.h>
#include <cstdint>
#include <math.h>

// Problem constants
#define BQ      4
#define NT      4096
#define CC      768
#define NHEADS  12
#define NPTS    4
#define HDIM    64
#define HIDDEN  3072
#define MROWS   (BQ*NT)          // 16384
#define SCALE_ATTN 0.125f        // 64^-0.5

// ---------------- scratch (device globals; no cudaMalloc allowed) ----------
__device__ float g_h[(size_t)MROWS * CC];          // ln1 out / ln2 out (reused)
__device__ float g_qkv[(size_t)MROWS * 3 * CC];    // qkv
__device__ float g_off[(size_t)MROWS * NHEADS * NPTS * 2];
__device__ float g_attn[(size_t)MROWS * CC];       // attention output
__device__ float g_mlp[(size_t)MROWS * HIDDEN];    // gelu(fc1)

// ---------------- LayerNorm: one 256-thread block per row (768 elems) ------
__global__ __launch_bounds__(256) void layernorm_kernel(
    const float* __restrict__ x, const float* __restrict__ w,
    const float* __restrict__ b, float* __restrict__ out)
{
    int row = blockIdx.x;
    int t = threadIdx.x;
    const float* xr = x + (size_t)row * CC;
    float v0 = xr[t], v1 = xr[t + 256], v2 = xr[t + 512];
    float s  = v0 + v1 + v2;
    float sq = v0*v0 + v1*v1 + v2*v2;

    __shared__ float sh[16];
    #pragma unroll
    for (int o = 16; o > 0; o >>= 1) {
        s  += __shfl_xor_sync(0xffffffffu, s,  o);
        sq += __shfl_xor_sync(0xffffffffu, sq, o);
    }
    int wid = t >> 5, lane = t & 31;
    if (lane == 0) { sh[wid] = s; sh[8 + wid] = sq; }
    __syncthreads();
    if (t == 0) {
        float ts = 0.f, tq = 0.f;
        #pragma unroll
        for (int i = 0; i < 8; i++) { ts += sh[i]; tq += sh[8 + i]; }
        sh[0] = ts; sh[8] = tq;
    }
    __syncthreads();
    float mean = sh[0] * (1.0f / CC);
    float var  = sh[8] * (1.0f / CC) - mean * mean;
    float rstd = rsqrtf(var + 1e-5f);
    float* orow = out + (size_t)row * CC;
    orow[t]       = (v0 - mean) * rstd * w[t]       + b[t];
    orow[t + 256] = (v1 - mean) * rstd * w[t + 256] + b[t + 256];
    orow[t + 512] = (v2 - mean) * rstd * w[t + 512] + b[t + 512];
}

// ============================================================================
// TF32 tensor-core GEMM: C[M,N] = A[M,K] * W[N,K]^T + bias (+epilogue)
// Requires M%128==0, N%128==0, K%16==0.
// EPI: 0 = bias, 1 = bias + exact GELU, 2 = bias + residual add
// 256 threads = 8 warps; block tile 128x128x16; warp tile 32x64;
// mma.sync.m16n8k8 tf32, fp32 accumulate; cp.async double-buffered.
// ============================================================================
#define TBM 128
#define TBN 128
#define TBK 16
#define TSTR 20   // smem row stride in floats (16 + 4 pad: 16B-aligned, conflict-free)

__device__ __forceinline__ void cp_async16(void* smem_dst, const void* gmem_src) {
    uint32_t s = (uint32_t)__cvta_generic_to_shared(smem_dst);
    asm volatile("cp.async.cg.shared.global [%0], [%1], 16;\n" :: "r"(s), "l"(gmem_src));
}
__device__ __forceinline__ uint32_t f2tf32(float f) {
    uint32_t u;
    asm("cvt.rna.tf32.f32 %0, %1;\n" : "=r"(u) : "f"(f));
    return u;
}

template<int EPI>
__global__ __launch_bounds__(256) void tf32gemm_nt(
    const float* __restrict__ A, int lda,
    const float* __restrict__ Bw,           // [N, K], K contiguous
    const float* __restrict__ bias,
    const float* __restrict__ Res, int ldr,
    float* __restrict__ C, int ldc,
    int K)
{
    __shared__ float As[2][TBM][TSTR];
    __shared__ float Bs[2][TBN][TSTR];

    const int t = threadIdx.x;
    const int rowTile = blockIdx.y * TBM;
    const int colTile = blockIdx.x * TBN;

    const int warp = t >> 5, lane = t & 31;
    const int wm = (warp & 3) * 32;       // warp M offset (4 warps along M)
    const int wn = (warp >> 2) * 64;      // warp N offset (2 warps along N)
    const int g  = lane >> 2;             // 0..7
    const int t4 = lane & 3;              // 0..3

    float acc[2][8][4];
    #pragma unroll
    for (int i = 0; i < 2; i++)
        #pragma unroll
        for (int j = 0; j < 8; j++)
            #pragma unroll
            for (int r = 0; r < 4; r++) acc[i][j][r] = 0.f;

    const int NK = K / TBK;

    // each thread copies 2 x 16B chunks per matrix per tile
    const int c0 = t, c1 = t + 256;       // chunk ids in [0,512)
    const int r0 = c0 >> 2, kc0 = (c0 & 3) * 4;
    const int r1 = c1 >> 2, kc1 = (c1 & 3) * 4;

    auto load_tile = [&](int kt, int buf) {
        const int kk = kt * TBK;
        cp_async16(&As[buf][r0][kc0], A  + (size_t)(rowTile + r0) * lda + kk + kc0);
        cp_async16(&As[buf][r1][kc1], A  + (size_t)(rowTile + r1) * lda + kk + kc1);
        cp_async16(&Bs[buf][r0][kc0], Bw + (size_t)(colTile + r0) * K   + kk + kc0);
        cp_async16(&Bs[buf][r1][kc1], Bw + (size_t)(colTile + r1) * K   + kk + kc1);
    };

    load_tile(0, 0);
    asm volatile("cp.async.commit_group;\n");

    for (int kt = 0; kt < NK; kt++) {
        const int cur = kt & 1;
        if (kt + 1 < NK) {
            load_tile(kt + 1, cur ^ 1);
            asm volatile("cp.async.commit_group;\n");
            asm volatile("cp.async.wait_group 1;\n");
        } else {
            asm volatile("cp.async.wait_group 0;\n");
        }
        __syncthreads();

        #pragma unroll
        for (int ks = 0; ks < 2; ks++) {
            const int k0 = ks * 8;
            // A fragments: 2 x m16
            uint32_t afr[2][4];
            #pragma unroll
            for (int i = 0; i < 2; i++) {
                int rr = wm + i * 16 + g;
                afr[i][0] = f2tf32(As[cur][rr    ][k0 + t4]);
                afr[i][1] = f2tf32(As[cur][rr + 8][k0 + t4]);
                afr[i][2] = f2tf32(As[cur][rr    ][k0 + t4 + 4]);
                afr[i][3] = f2tf32(As[cur][rr + 8][k0 + t4 + 4]);
            }
            // B fragments: 8 x n8
            uint32_t bfr[8][2];
            #pragma unroll
            for (int j = 0; j < 8; j++) {
                int cc = wn + j * 8 + g;
                bfr[j][0] = f2tf32(Bs[cur][cc][k0 + t4]);
                bfr[j][1] = f2tf32(Bs[cur][cc][k0 + t4 + 4]);
            }
            #pragma unroll
            for (int i = 0; i < 2; i++)
                #pragma unroll
                for (int j = 0; j < 8; j++) {
                    asm volatile(
                        "mma.sync.aligned.m16n8k8.row.col.f32.tf32.tf32.f32 "
                        "{%0,%1,%2,%3}, {%4,%5,%6,%7}, {%8,%9}, {%0,%1,%2,%3};\n"
                        : "+f"(acc[i][j][0]), "+f"(acc[i][j][1]),
                          "+f"(acc[i][j][2]), "+f"(acc[i][j][3])
                        : "r"(afr[i][0]), "r"(afr[i][1]), "r"(afr[i][2]), "r"(afr[i][3]),
                          "r"(bfr[j][0]), "r"(bfr[j][1]));
                }
        }
        __syncthreads();
    }

    // epilogue: acc[i][j] covers rows {wm+i*16+g, +8}, cols {wn+j*8+2*t4, +1}
    #pragma unroll
    for (int i = 0; i < 2; i++) {
        #pragma unroll
        for (int half = 0; half < 2; half++) {
            int r = rowTile + wm + i * 16 + g + half * 8;
            float* crow = C + (size_t)r * ldc;
            const float* rrow = (EPI == 2) ? (Res + (size_t)r * ldr) : nullptr;
            #pragma unroll
            for (int j = 0; j < 8; j++) {
                int cg = colTile + wn + j * 8 + t4 * 2;
                float v0 = acc[i][j][half * 2 + 0] + bias[cg];
                float v1 = acc[i][j][half * 2 + 1] + bias[cg + 1];
                if (EPI == 1) {
                    v0 = 0.5f * v0 * (1.0f + erff(v0 * 0.70710678118654752f));
                    v1 = 0.5f * v1 * (1.0f + erff(v1 * 0.70710678118654752f));
                }
                if (EPI == 2) { v0 += rrow[cg]; v1 += rrow[cg + 1]; }
                *(float2*)(crow + cg) = make_float2(v0, v1);
            }
        }
    }
}

// ---------------- fp32 SGEMM (kept for the small N=96 offsets GEMM) --------
template<int EPI>
__global__ __launch_bounds__(256) void sgemm_nt(
    const float* __restrict__ A, int lda,
    const float* __restrict__ Bw,
    const float* __restrict__ bias,
    const float* __restrict__ Res, int ldr,
    float* __restrict__ C, int ldc,
    int M, int N, int K)
{
    __shared__ float As[8][128];
    __shared__ float Bs[8][128];

    int t = threadIdx.x;
    int rowTile = blockIdx.y * 128;
    int colTile = blockIdx.x * 128;

    int ldRow = t >> 1;
    int ldCol = (t & 1) * 4;

    const float* Aptr = A + (size_t)(rowTile + ldRow) * lda + ldCol;
    bool bValid = (colTile + ldRow) < N;
    const float* Bptr = Bw + (size_t)(colTile + ldRow) * K + ldCol;

    int ty = t >> 4, tx = t & 15;
    float acc[8][8];
    #pragma unroll
    for (int i = 0; i < 8; i++)
        #pragma unroll
        for (int j = 0; j < 8; j++) acc[i][j] = 0.f;

    for (int k0 = 0; k0 < K; k0 += 8) {
        float4 av = *(const float4*)(Aptr + k0);
        float4 bv = bValid ? *(const float4*)(Bptr + k0)
                           : make_float4(0.f, 0.f, 0.f, 0.f);
        As[ldCol + 0][ldRow] = av.x; As[ldCol + 1][ldRow] = av.y;
        As[ldCol + 2][ldRow] = av.z; As[ldCol + 3][ldRow] = av.w;
        Bs[ldCol + 0][ldRow] = bv.x; Bs[ldCol + 1][ldRow] = bv.y;
        Bs[ldCol + 2][ldRow] = bv.z; Bs[ldCol + 3][ldRow] = bv.w;
        __syncthreads();

        #pragma unroll
        for (int k = 0; k < 8; k++) {
            float4 a0 = *(const float4*)&As[k][ty * 8];
            float4 a1 = *(const float4*)&As[k][ty * 8 + 4];
            float4 b0 = *(const float4*)&Bs[k][tx * 8];
            float4 b1 = *(const float4*)&Bs[k][tx * 8 + 4];
            float ar[8] = {a0.x, a0.y, a0.z, a0.w, a1.x, a1.y, a1.z, a1.w};
            float br[8] = {b0.x, b0.y, b0.z, b0.w, b1.x, b1.y, b1.z, b1.w};
            #pragma unroll
            for (int i = 0; i < 8; i++)
                #pragma unroll
                for (int j = 0; j < 8; j++)
                    acc[i][j] = fmaf(ar[i], br[j], acc[i][j]);
        }
        __syncthreads();
    }

    #pragma unroll
    for (int i = 0; i < 8; i++) {
        int r = rowTile + ty * 8 + i;
        float* crow = C + (size_t)r * ldc;
        const float* rrow = (EPI == 2) ? (Res + (size_t)r * ldr) : nullptr;
        #pragma unroll
        for (int j = 0; j < 8; j++) {
            int c = colTile + tx * 8 + j;
            if (c < N) {
                float v = acc[i][j] + bias[c];
                if (EPI == 1) v = 0.5f * v * (1.0f + erff(v * 0.70710678118654752f));
                if (EPI == 2) v += rrow[c];
                crow[c] = v;
            }
        }
    }
}

// ---------------- deformable sampling + attention --------------------------
__global__ __launch_bounds__(32) void attn_kernel(
    const float* __restrict__ qkv,    // [M, 2304]
    const float* __restrict__ off,    // [M, 96]
    const float* __restrict__ refp,   // [M, 2]
    float* __restrict__ out,          // [M, 768]
    const int* __restrict__ Hp, const int* __restrict__ Wp)
{
    int bn   = blockIdx.x;
    int head = blockIdx.y;
    int lane = threadIdx.x;
    int b = bn / NT;

    int H = *Hp, W = *Wp;
    float fW = (float)W, fH = (float)H;

    size_t qbase = (size_t)bn * (3 * CC) + head * HDIM;
    float q0 = qkv[qbase + lane];
    float q1 = qkv[qbase + lane + 32];

    float ref0 = refp[(size_t)bn * 2 + 0];
    float ref1 = refp[(size_t)bn * 2 + 1];

    const float* offp = off + (size_t)bn * (NHEADS * NPTS * 2) + head * (NPTS * 2);

    float dots[NPTS];
    float sv0[NPTS], sv1[NPTS];

    #pragma unroll
    for (int p = 0; p < NPTS; p++) {
        float o0 = offp[p * 2 + 0];
        float o1 = offp[p * 2 + 1];
        float gx = 2.0f * (ref0 + o0 / fW) - 1.0f;
        float gy = 2.0f * (ref1 + o1 / fH) - 1.0f;
        float x = ((gx + 1.0f) * fW - 1.0f) * 0.5f;
        float y = ((gy + 1.0f) * fH - 1.0f) * 0.5f;
        float x0f = floorf(x), y0f = floorf(y);
        float wx = x - x0f, wy = y - y0f;
        int x0 = (int)x0f, y0 = (int)y0f;

        float cw[4] = {(1.f - wx) * (1.f - wy), wx * (1.f - wy),
                       (1.f - wx) * wy,          wx * wy};
        int cx[4] = {x0, x0 + 1, x0,     x0 + 1};
        int cy[4] = {y0, y0,     y0 + 1, y0 + 1};

        float sk0 = 0.f, sk1 = 0.f, vv0 = 0.f, vv1 = 0.f;
        #pragma unroll
        for (int c = 0; c < 4; c++) {
            int ix = cx[c], iy = cy[c];
            if (ix >= 0 && ix < W && iy >= 0 && iy < H) {
                size_t rb = ((size_t)(b * NT + iy * W + ix)) * (3 * CC) + head * HDIM;
                const float* kp = qkv + rb + CC;
                const float* vp = qkv + rb + 2 * CC;
                float w = cw[c];
                sk0 = fmaf(w, kp[lane],      sk0);
                sk1 = fmaf(w, kp[lane + 32], sk1);
                vv0 = fmaf(w, vp[lane],      vv0);
                vv1 = fmaf(w, vp[lane + 32], vv1);
            }
        }
        sv0[p] = vv0; sv1[p] = vv1;

        float dot = q0 * sk0 + q1 * sk1;
        #pragma unroll
        for (int o = 16; o > 0; o >>= 1)
            dot += __shfl_xor_sync(0xffffffffu, dot, o);
        dots[p] = dot * SCALE_ATTN;
    }

    float mx = fmaxf(fmaxf(dots[0], dots[1]), fmaxf(dots[2], dots[3]));
    float e[NPTS], es = 0.f;
    #pragma unroll
    for (int p = 0; p < NPTS; p++) { e[p] = __expf(dots[p] - mx); es += e[p]; }
    float inv = 1.0f / es;

    float out0 = 0.f, out1 = 0.f;
    #pragma unroll
    for (int p = 0; p < NPTS; p++) {
        float a = e[p] * inv;
        out0 = fmaf(a, sv0[p], out0);
        out1 = fmaf(a, sv1[p], out1);
    }
    size_t ob = (size_t)bn * CC + head * HDIM;
    out[ob + lane]      = out0;
    out[ob + lane + 32] = out1;
}

// ---------------- launch ----------------------------------------------------
extern "C" void kernel_launch(void* const* d_in, const int* in_sizes, int n_in,
                              void* d_out, int out_size)
{
    const float* x      = (const float*)d_in[0];
    const float* refp   = (const float*)d_in[1];
    const float* n1w    = (const float*)d_in[2];
    const float* n1b    = (const float*)d_in[3];
    const float* qkv_w  = (const float*)d_in[4];
    const float* qkv_b  = (const float*)d_in[5];
    const float* off_w  = (const float*)d_in[6];
    const float* off_b  = (const float*)d_in[7];
    const float* proj_w = (const float*)d_in[8];
    const float* proj_b = (const float*)d_in[9];
    const float* n2w    = (const float*)d_in[10];
    const float* n2b    = (const float*)d_in[11];
    const float* fc1_w  = (const float*)d_in[12];
    const float* fc1_b  = (const float*)d_in[13];
    const float* fc2_w  = (const float*)d_in[14];
    const float* fc2_b  = (const float*)d_in[15];
    const int*   Hp     = (const int*)d_in[16];
    const int*   Wp     = (const int*)d_in[17];
    float* out = (float*)d_out;

    float* h    = nullptr; cudaGetSymbolAddress((void**)&h,    g_h);
    float* qkv  = nullptr; cudaGetSymbolAddress((void**)&qkv,  g_qkv);
    float* offb = nullptr; cudaGetSymbolAddress((void**)&offb, g_off);
    float* attn = nullptr; cudaGetSymbolAddress((void**)&attn, g_attn);
    float* mlp  = nullptr; cudaGetSymbolAddress((void**)&mlp,  g_mlp);

    // 1) ln1: x -> h
    layernorm_kernel<<<MROWS, 256>>>(x, n1w, n1b, h);

    // 2) qkv = h @ qkv_w^T + b : [16384, 2304]   (tf32 tensor cores)
    {
        dim3 grid((3 * CC) / TBN, MROWS / TBM);
        tf32gemm_nt<0><<<grid, 256>>>(h, CC, qkv_w, qkv_b,
                                      nullptr, 0, qkv, 3 * CC, CC);
    }

    // 3) offsets = q @ off_w^T + off_b : [16384, 96]  (small; fp32 path)
    {
        dim3 grid(1, MROWS / 128);
        sgemm_nt<0><<<grid, 256>>>(qkv, 3 * CC, off_w, off_b,
                                   nullptr, 0, offb, NHEADS * NPTS * 2,
                                   MROWS, NHEADS * NPTS * 2, CC);
    }

    // 4) deformable sampling + attention -> attn [16384, 768]
    {
        dim3 grid(BQ * NT, NHEADS);
        attn_kernel<<<grid, 32>>>(qkv, offb, refp, attn, Hp, Wp);
    }

    // 5) x1 = x + attn @ proj_w^T + proj_b -> out   (tf32)
    {
        dim3 grid(CC / TBN, MROWS / TBM);
        tf32gemm_nt<2><<<grid, 256>>>(attn, CC, proj_w, proj_b,
                                      x, CC, out, CC, CC);
    }

    // 6) ln2: out -> h
    layernorm_kernel<<<MROWS, 256>>>(out, n2w, n2b, h);

    // 7) m = gelu(h @ fc1_w^T + fc1_b) -> mlp [16384, 3072]   (tf32)
    {
        dim3 grid(HIDDEN / TBN, MROWS / TBM);
        tf32gemm_nt<1><<<grid, 256>>>(h, CC, fc1_w, fc1_b,
                                      nullptr, 0, mlp, HIDDEN, CC);
    }

    // 8) out = out + mlp @ fc2_w^T + fc2_b   (tf32)
    {
        dim3 grid(CC / TBN, MROWS / TBM);
        tf32gemm_nt<2><<<grid, 256>>>(mlp, HIDDEN, fc2_w, fc2_b,
                                      out, CC, out, CC, HIDDEN);
    }
}